// round 2
// baseline (speedup 1.0000x reference)
#include <cuda_runtime.h>
#include <math.h>

#define Bn 64
#define Hn 512
#define En 256
#define Vn 32000
#define Sn 64
#define NVB 250   /* Vn / 128 v-blocks in logits kernel */

// ---------------- persistent device state (no cudaMalloc allowed) ------------
__device__ float g_h[2][Bn * Hn];        // double-buffered hidden state
__device__ float g_c[Bn * Hn];           // cell state
__device__ float g_gates[4 * Hn * Bn];   // gate accumulator, layout [row][b]
__device__ float g_pval[Bn * NVB];       // argmax partials (value)
__device__ int   g_pidx[Bn * NVB];       // argmax partials (index)
__device__ int   g_tf[Sn];               // decoded use_tf flags

__device__ __forceinline__ float sigmoidf_(float x) {
    return 1.0f / (1.0f + expf(-x));
}

// ---- Blackwell packed fp32x2 helpers ----------------------------------------
__device__ __forceinline__ unsigned long long pk2(float lo, float hi) {
    unsigned long long r;
    asm("mov.b64 %0, {%1, %2};" : "=l"(r) : "f"(lo), "f"(hi));
    return r;
}
__device__ __forceinline__ void up2(float& lo, float& hi, unsigned long long v) {
    asm("mov.b64 {%0, %1}, %2;" : "=f"(lo), "=f"(hi) : "l"(v));
}
__device__ __forceinline__ void ffma2(unsigned long long& acc,
                                      unsigned long long a,
                                      unsigned long long b) {
    asm("fma.rn.f32x2 %0, %1, %2, %0;" : "+l"(acc) : "l"(a), "l"(b));
}

// ---------------- init: decode use_tf layout, zero scratch + out[:,0,:] ------
__global__ void init_kernel(const unsigned char* tf_raw, float* out) {
    if (blockIdx.x == 0) {
        __shared__ int mode;  // 0 = 1-byte bool, 1 = 4-byte word
        if (threadIdx.x == 0) {
            int gt1 = 0, odd1 = 0;
            for (int i = 0; i < Sn; i++) {
                unsigned char v = tf_raw[i];
                if (v > 1) gt1 = 1;
                if (v == 1 && (i & 3)) odd1 = 1;
            }
            mode = gt1 ? 1 : (odd1 ? 0 : 1);
        }
        __syncthreads();
        if (threadIdx.x < Sn) {
            int t = threadIdx.x;
            int val;
            if (mode == 0) val = (tf_raw[t] != 0);
            else           val = (((const unsigned int*)tf_raw)[t] != 0u);
            g_tf[t] = val;
        }
    }
    for (int i = blockIdx.x * blockDim.x + threadIdx.x; i < 4 * Hn * Bn;
         i += gridDim.x * blockDim.x)
        g_gates[i] = 0.0f;
    for (int i = blockIdx.x * blockDim.x + threadIdx.x; i < Bn * Vn;
         i += gridDim.x * blockDim.x) {
        int b = i / Vn, v = i - b * Vn;
        out[(size_t)b * Sn * Vn + v] = 0.0f;
    }
}

// ---------------- gates: split-K GEMM with atomic accumulation ---------------
// grid (16 j-blocks, 6 k-slices) x 256 threads.
__global__ __launch_bounds__(256) void gates_kernel(
    int k, const int* __restrict__ captions, const float* __restrict__ emb,
    const float* __restrict__ W_ih, const float* __restrict__ W_hh,
    const float* __restrict__ enc)
{
    __shared__ float xh_s[32][68];   // [kk][b]
    __shared__ float w_s[32][132];   // [kk][row]
    __shared__ int   tok_s[Bn];

    int tid = threadIdx.x;
    int j0 = blockIdx.x * 32;
    int slice = blockIdx.y;
    bool xpart = (slice < 2);
    int kslice0 = xpart ? slice * 128 : (slice - 2) * 128;

    if (xpart) {
        if (k == 0) {
            if (tid < Bn) tok_s[tid] = captions[tid * Sn + 0];
        } else {
            int b = tid >> 2, l4 = tid & 3;
            float bv = -3.4e38f; int bi = 0x7fffffff;
            for (int p = l4; p < NVB; p += 4) {
                float v = g_pval[b * NVB + p];
                int  ii = g_pidx[b * NVB + p];
                if (v > bv || (v == bv && ii < bi)) { bv = v; bi = ii; }
            }
            #pragma unroll
            for (int off = 2; off > 0; off >>= 1) {
                float ov = __shfl_down_sync(0xffffffffu, bv, off, 4);
                int   oi = __shfl_down_sync(0xffffffffu, bi, off, 4);
                if (ov > bv || (ov == bv && oi < bi)) { bv = ov; bi = oi; }
            }
            if (l4 == 0)
                tok_s[b] = g_tf[k] ? captions[b * Sn + k] : bi;
        }
    }
    __syncthreads();

    unsigned long long acc2[4][4];
    #pragma unroll
    for (int g = 0; g < 4; g++)
        #pragma unroll
        for (int p = 0; p < 4; p++) acc2[g][p] = 0ull;

    int jj = tid & 31, bb = tid >> 5;

    for (int t8 = 0; t8 < 4; t8++) {
        int kb = t8 * 32;
        {
            int b = tid >> 2, kq = tid & 3;
            int kk0 = kq * 8;
            if (xpart) {
                int tok = tok_s[b];
                const float* row = emb + (size_t)tok * En;
                #pragma unroll
                for (int i = 0; i < 8; i++) {
                    int kg = kslice0 + kb + kk0 + i;
                    xh_s[kk0 + i][b] = (tok == 0) ? 0.0f : row[kg];
                }
            } else {
                const float* hsrc = (k == 0) ? (enc + b * Hn) : (&g_h[k & 1][b * Hn]);
                #pragma unroll
                for (int i = 0; i < 8; i++) {
                    int kg = kslice0 + kb + kk0 + i;
                    xh_s[kk0 + i][b] = hsrc[kg];
                }
            }
        }
        {
            int k4 = tid & 7, r0 = tid >> 3;
            #pragma unroll
            for (int pass = 0; pass < 4; pass++) {
                int r = r0 + pass * 32;
                int gate = r >> 5;
                int R = gate * Hn + j0 + (r & 31);
                int kg = kslice0 + kb + k4 * 4;
                const float* wptr = xpart ? (W_ih + (size_t)R * En + kg)
                                          : (W_hh + (size_t)R * Hn + kg);
                float4 w4 = *(const float4*)wptr;
                w_s[k4 * 4 + 0][r] = w4.x;
                w_s[k4 * 4 + 1][r] = w4.y;
                w_s[k4 * 4 + 2][r] = w4.z;
                w_s[k4 * 4 + 3][r] = w4.w;
            }
        }
        __syncthreads();
        #pragma unroll
        for (int kk = 0; kk < 32; kk++) {
            unsigned long long wp[4];
            #pragma unroll
            for (int g = 0; g < 4; g++) {
                float w = w_s[kk][g * 32 + jj];
                wp[g] = pk2(w, w);
            }
            ulonglong2 h01 = *(const ulonglong2*)&xh_s[kk][bb * 8];
            ulonglong2 h23 = *(const ulonglong2*)&xh_s[kk][bb * 8 + 4];
            unsigned long long hd[4] = {h01.x, h01.y, h23.x, h23.y};
            #pragma unroll
            for (int g = 0; g < 4; g++)
                #pragma unroll
                for (int p = 0; p < 4; p++)
                    ffma2(acc2[g][p], wp[g], hd[p]);
        }
        __syncthreads();
    }

    #pragma unroll
    for (int g = 0; g < 4; g++) {
        int R = g * Hn + j0 + jj;
        #pragma unroll
        for (int p = 0; p < 4; p++) {
            float lo, hi;
            up2(lo, hi, acc2[g][p]);
            atomicAdd(&g_gates[R * Bn + bb * 8 + 2 * p], lo);
            atomicAdd(&g_gates[R * Bn + bb * 8 + 2 * p + 1], hi);
        }
    }
}

// ---------------- cell update; also re-zeros gate accumulator ----------------
__global__ __launch_bounds__(256) void cell_kernel(
    int k, const float* __restrict__ b_ih, const float* __restrict__ b_hh)
{
    int idx = blockIdx.x * 256 + threadIdx.x;
    int b = idx & 63;
    int j = idx >> 6;

    float gi = g_gates[(0 * Hn + j) * Bn + b] + b_ih[0 * Hn + j] + b_hh[0 * Hn + j];
    float gf = g_gates[(1 * Hn + j) * Bn + b] + b_ih[1 * Hn + j] + b_hh[1 * Hn + j];
    float gg = g_gates[(2 * Hn + j) * Bn + b] + b_ih[2 * Hn + j] + b_hh[2 * Hn + j];
    float go = g_gates[(3 * Hn + j) * Bn + b] + b_ih[3 * Hn + j] + b_hh[3 * Hn + j];

    float c_old = (k == 0) ? 0.0f : g_c[b * Hn + j];
    float c = sigmoidf_(gf) * c_old + sigmoidf_(gi) * tanhf(gg);
    float h = sigmoidf_(go) * tanhf(c);
    g_c[b * Hn + j] = c;
    g_h[(k + 1) & 1][b * Hn + j] = h;

    g_gates[(0 * Hn + j) * Bn + b] = 0.0f;
    g_gates[(1 * Hn + j) * Bn + b] = 0.0f;
    g_gates[(2 * Hn + j) * Bn + b] = 0.0f;
    g_gates[(3 * Hn + j) * Bn + b] = 0.0f;
}

// ---------------- logits GEMM + argmax partials (FFMA2, 128v x 64b tile) -----
// grid 250 x 256 threads. Thread tile 8v (4 f32x2 pairs) x 4b.
__global__ __launch_bounds__(256) void logits_kernel(
    int k, const float* __restrict__ fc_w, const float* __restrict__ fc_b,
    float* __restrict__ out)
{
    __shared__ float w_s[16][132];  // [kk][v], padded
    __shared__ float h_s[16][68];   // [kk][b], padded
    int tid = threadIdx.x;
    int v0 = blockIdx.x * 128;
    int tv = tid & 15, tb = tid >> 4;
    const float* hcur = g_h[(k + 1) & 1];

    unsigned long long acc2[4][4];  // [vpair][b]
    #pragma unroll
    for (int i = 0; i < 4; i++)
        #pragma unroll
        for (int j = 0; j < 4; j++) acc2[i][j] = 0ull;

    for (int t8 = 0; t8 < 32; t8++) {
        int kb = t8 * 16;
        // fill W tile: 128 v x 16 k
        {
            int k4 = tid & 3, vv0 = tid >> 2;  // vv0: 0..63
            #pragma unroll
            for (int pass = 0; pass < 2; pass++) {
                int vv = vv0 + pass * 64;
                float4 w4 = *(const float4*)(fc_w + (size_t)(v0 + vv) * Hn + kb + k4 * 4);
                w_s[k4 * 4 + 0][vv] = w4.x;
                w_s[k4 * 4 + 1][vv] = w4.y;
                w_s[k4 * 4 + 2][vv] = w4.z;
                w_s[k4 * 4 + 3][vv] = w4.w;
            }
        }
        // fill h tile: 64 b x 16 k
        {
            int b = tid >> 2, kq = tid & 3;
            float4 a = *(const float4*)(hcur + b * Hn + kb + kq * 4);
            h_s[kq * 4 + 0][b] = a.x;
            h_s[kq * 4 + 1][b] = a.y;
            h_s[kq * 4 + 2][b] = a.z;
            h_s[kq * 4 + 3][b] = a.w;
        }
        __syncthreads();
        #pragma unroll
        for (int kk = 0; kk < 16; kk++) {
            ulonglong2 wA = *(const ulonglong2*)&w_s[kk][tv * 8];
            ulonglong2 wB = *(const ulonglong2*)&w_s[kk][tv * 8 + 4];
            unsigned long long wd[4] = {wA.x, wA.y, wB.x, wB.y};
            float4 hv = *(const float4*)&h_s[kk][tb * 4];
            unsigned long long hd[4] = {pk2(hv.x, hv.x), pk2(hv.y, hv.y),
                                        pk2(hv.z, hv.z), pk2(hv.w, hv.w)};
            #pragma unroll
            for (int i = 0; i < 4; i++)
                #pragma unroll
                for (int j = 0; j < 4; j++)
                    ffma2(acc2[i][j], wd[i], hd[j]);
        }
        __syncthreads();
    }

    int t = k + 1;
    float bias[8];
    #pragma unroll
    for (int i = 0; i < 8; i++) bias[i] = fc_b[v0 + tv * 8 + i];

    #pragma unroll
    for (int j = 0; j < 4; j++) {
        int b = tb * 4 + j;
        float vals[8];
        #pragma unroll
        for (int i = 0; i < 4; i++) {
            float lo, hi;
            up2(lo, hi, acc2[i][j]);
            vals[2 * i]     = lo + bias[2 * i];
            vals[2 * i + 1] = hi + bias[2 * i + 1];
        }

        float4 r0 = make_float4(vals[0], vals[1], vals[2], vals[3]);
        float4 r1 = make_float4(vals[4], vals[5], vals[6], vals[7]);
        float* obase = out + ((size_t)b * Sn + t) * Vn + v0 + tv * 8;
        *(float4*)obase = r0;
        *(float4*)(obase + 4) = r1;

        // per-b argmax partial over this block's 128 v (lowest index on ties)
        float bv = vals[0]; int bi = v0 + tv * 8;
        #pragma unroll
        for (int i = 1; i < 8; i++) {
            int vi = v0 + tv * 8 + i;
            if (vals[i] > bv) { bv = vals[i]; bi = vi; }
        }
        #pragma unroll
        for (int off = 8; off > 0; off >>= 1) {
            float ov = __shfl_down_sync(0xffffffffu, bv, off, 16);
            int   oi = __shfl_down_sync(0xffffffffu, bi, off, 16);
            if (ov > bv || (ov == bv && oi < bi)) { bv = ov; bi = oi; }
        }
        if (tv == 0) {
            g_pval[b * NVB + blockIdx.x] = bv;
            g_pidx[b * NVB + blockIdx.x] = bi;
        }
    }
}

// ---------------- launch ------------------------------------------------------
extern "C" void kernel_launch(void* const* d_in, const int* in_sizes, int n_in,
                              void* d_out, int out_size) {
    (void)in_sizes; (void)n_in; (void)out_size;
    const float*         enc  = (const float*)d_in[0];
    const int*           caps = (const int*)d_in[1];
    const unsigned char* tf   = (const unsigned char*)d_in[2];
    const float*         emb  = (const float*)d_in[3];
    const float*         W_ih = (const float*)d_in[4];
    const float*         W_hh = (const float*)d_in[5];
    const float*         b_ih = (const float*)d_in[6];
    const float*         b_hh = (const float*)d_in[7];
    const float*         fc_w = (const float*)d_in[8];
    const float*         fc_b = (const float*)d_in[9];
    float* out = (float*)d_out;

    init_kernel<<<512, 256>>>(tf, out);
    dim3 gGrid(16, 6);
    for (int k = 0; k < 63; k++) {
        gates_kernel<<<gGrid, 256>>>(k, caps, emb, W_ih, W_hh, enc);
        cell_kernel<<<128, 256>>>(k, b_ih, b_hh);
        logits_kernel<<<250, 256>>>(k, fc_w, fc_b, out);
    }
}